// round 17
// baseline (speedup 1.0000x reference)
#include <cuda_runtime.h>
#include <cuda_bf16.h>
#include <cstdint>

#define Hn    250       // hidden units
#define Bn    256       // batch
#define Tn    512       // time steps
#define Gn    1000      // 4*H gate rows
#define HP    256       // padded hidden stride (u64 pairs)
#define KP    252       // padded K for recurrent GEMM
#define KCn   63        // KP/4 chunks

// ---------------- scratch (device globals; zero-initialized at load) ----------------
__device__ float              g_xg[(size_t)Tn * Bn * Gn];          // input-gate contributions (xg0, overwritten per-t with xg1)
__device__ unsigned long long g_hd[(size_t)(Tn + 1) * Bn * HP];    // duplicated {h,h} pairs (both layers reuse; slice 0 zeros)
__device__ unsigned           g_cnt [2][8][32];                    // per-(layer, batch-group) monotone arrive counters
__device__ unsigned           g_flag[2][8][32];                    // per-(layer, batch-group) monotone epoch flags

// ---------------- helpers ----------------
__device__ __forceinline__ float sigf(float x) { return 1.f / (1.f + __expf(-x)); }
__device__ __forceinline__ float tanhfast(float x) { return 1.f - 2.f / (__expf(2.f * x) + 1.f); }

__device__ __forceinline__ unsigned long long pack2(float lo, float hi) {
    unsigned long long r;
    asm("mov.b64 %0, {%1, %2};" : "=l"(r) : "f"(lo), "f"(hi));
    return r;
}
__device__ __forceinline__ void unpack2(unsigned long long v, float& lo, float& hi) {
    asm("mov.b64 {%0, %1}, %2;" : "=f"(lo), "=f"(hi) : "l"(v));
}
__device__ __forceinline__ void ffma2(unsigned long long& acc, unsigned long long a, unsigned long long b) {
    asm("fma.rn.f32x2 %0, %1, %2, %0;" : "+l"(acc) : "l"(a), "l"(b));
}
__device__ __forceinline__ unsigned long long add2(unsigned long long a, unsigned long long b) {
    unsigned long long r;
    asm("add.rn.f32x2 %0, %1, %2;" : "=l"(r) : "l"(a), "l"(b));
    return r;
}

// Transposed, gate-interleaved weight tile: sW[k*64 + m], m = u_local*4 + g.
__device__ void fill_WT(float* sW, const float* __restrict__ W, int u0, int Kreal, int kc_n) {
    int total = 64 * kc_n;
    for (int i = threadIdx.x; i < total; i += blockDim.x) {
        int m  = i / kc_n;
        int kc = i - m * kc_n;
        int k  = kc * 4;
        int g  = m & 3;
        int u  = u0 + (m >> 2);
        float4 v = make_float4(0.f, 0.f, 0.f, 0.f);
        if (u < Hn) {
            const float* src = W + (size_t)(g * Hn + u) * Kreal + k;
            if (k + 0 < Kreal) v.x = src[0];
            if (k + 1 < Kreal) v.y = src[1];
            if (k + 2 < Kreal) v.z = src[2];
            if (k + 3 < Kreal) v.w = src[3];
        }
        sW[(k + 0) * 64 + m] = v.x;
        sW[(k + 1) * 64 + m] = v.y;
        sW[(k + 2) * 64 + m] = v.z;
        sW[(k + 3) * 64 + m] = v.w;
    }
}

// ---------------- layer-0 input GEMM (K=40): 128 rows x 64 cols, 8-row register blocking ----------------
__global__ void __launch_bounds__(256, 1)
k_xgemm0(const float* __restrict__ A_in, const float* __restrict__ Wih,
         const float* __restrict__ bih, const float* __restrict__ bhh) {
    const int kc_n = 10, astride = 48;
    extern __shared__ float smem[];
    float* sW = smem;                          // 40 * 64
    float* sA = sW + kc_n * 4 * 64;            // 128 * 48
    float* sB = sA + 128 * astride;            // 64 bias
    int tid = threadIdx.x;
    int u0 = blockIdx.x * 16;
    int rbase = blockIdx.y * 128;

    fill_WT(sW, Wih, u0, 40, kc_n);
    if (tid < 64) {
        int g = tid & 3, u = u0 + (tid >> 2);
        sB[tid] = (u < Hn) ? (bih[g * Hn + u] + bhh[g * Hn + u]) : 0.f;
    }
    for (int i = tid; i < 128 * 10; i += 256) {
        int row = i / 10, c4 = i - row * 10;
        int r = rbase + row;
        int tt = r >> 8, b = r & 255;
        *(float4*)&sA[row * astride + c4 * 4] =
            __ldg((const float4*)(A_in + ((size_t)b * Tn + tt) * 40 + c4 * 4));
    }
    __syncthreads();

    int q = tid & 15, rg = tid >> 4;
    int r0 = rg * 8;
    unsigned long long acc_if[8], acc_go[8];
    #pragma unroll
    for (int rr = 0; rr < 8; ++rr) { acc_if[rr] = 0ull; acc_go[rr] = 0ull; }

    #pragma unroll
    for (int kc = 0; kc < kc_n; ++kc) {
        int k = kc * 4;
        ulonglong2 w0 = *(const ulonglong2*)&sW[(k + 0) * 64 + 4 * q];
        ulonglong2 w1 = *(const ulonglong2*)&sW[(k + 1) * 64 + 4 * q];
        ulonglong2 w2 = *(const ulonglong2*)&sW[(k + 2) * 64 + 4 * q];
        ulonglong2 w3 = *(const ulonglong2*)&sW[(k + 3) * 64 + 4 * q];
        #pragma unroll
        for (int rr = 0; rr < 8; ++rr) {
            float4 av = *(const float4*)&sA[(r0 + rr) * astride + k];
            unsigned long long h0 = pack2(av.x, av.x);
            unsigned long long h1 = pack2(av.y, av.y);
            unsigned long long h2 = pack2(av.z, av.z);
            unsigned long long h3 = pack2(av.w, av.w);
            ffma2(acc_if[rr], w0.x, h0); ffma2(acc_go[rr], w0.y, h0);
            ffma2(acc_if[rr], w1.x, h1); ffma2(acc_go[rr], w1.y, h1);
            ffma2(acc_if[rr], w2.x, h2); ffma2(acc_go[rr], w2.y, h2);
            ffma2(acc_if[rr], w3.x, h3); ffma2(acc_go[rr], w3.y, h3);
        }
    }

    int u = u0 + q;
    if (u < Hn) {
        float4 bv = *(const float4*)&sB[4 * q];
        #pragma unroll
        for (int rr = 0; rr < 8; ++rr) {
            float4 o; float lo, hi;
            unpack2(acc_if[rr], lo, hi); o.x = lo + bv.x; o.y = hi + bv.y;
            unpack2(acc_go[rr], lo, hi); o.z = lo + bv.z; o.w = hi + bv.w;
            *(float4*)(g_xg + ((size_t)(rbase + r0 + rr)) * Gn + u * 4) = o;
        }
    }
}

// ---------------- persistent recurrent kernel (optionally fused with next-layer input GEMM) ----------------
// 128 CTAs = 16 unit-tiles x 8 batch-groups (32 cols). 256 threads = (q 0..15, cg 0..7, kh 0..1).
// FUSED=1 (layer 0): the X-GEMM (xg1[t-1] = W_ih1 @ h0(t-1) + b) runs in the barrier
// ARRIVE->WAIT window, OFF the inter-CTA critical path (its output feeds only the next kernel).
template<int FUSED>
__global__ void __launch_bounds__(256, 1)
k_rec(const float* __restrict__ Whh, const float* __restrict__ Wih2,
      const float* __restrict__ bih2, const float* __restrict__ bhh2, int layer) {
    extern __shared__ float smem[];
    float* sW1 = smem;                                               // KP*64 f32     (64512 B)
    unsigned long long* sH = (unsigned long long*)(smem + KP * 64);  // 32*252 u64    (64512 B)
    unsigned long long* sRed = sH + 32 * KP;                         // 2048 u64      (16384 B)
    unsigned* sBase = (unsigned*)(sRed + 2048);                      // 16 B
    float* sW2 = (float*)((char*)smem + 145424);                     // KP*64 f32 (FUSED only)

    const float* xg = g_xg;

    int tid = threadIdx.x, lane = tid & 31, w = tid >> 5;
    int ut = blockIdx.x & 15, bt = blockIdx.x >> 4;
    int u0 = ut * 16, b0 = bt * 32;
    int q = tid & 15;
    int cg = (tid >> 4) & 7;        // GEMM col-group (4 cells)
    int kh = tid >> 7;              // K-half
    int cgf = tid >> 4;             // pointwise col-pair, 0..15
    int c0 = cgf * 2;
    int u = u0 + q;
    bool valid = (u < Hn);

    unsigned* cnt = &g_cnt[layer][bt][0];
    unsigned* flg = &g_flag[layer][bt][0];

    fill_WT(sW1, Whh, u0, Hn, KCn);
    if (FUSED) fill_WT(sW2, Wih2, u0, Hn, KCn);

    unsigned long long b2_if = 0ull, b2_go = 0ull;
    if (FUSED && valid) {
        b2_if = pack2(bih2[0 * Hn + u] + bhh2[0 * Hn + u], bih2[1 * Hn + u] + bhh2[1 * Hn + u]);
        b2_go = pack2(bih2[2 * Hn + u] + bhh2[2 * Hn + u], bih2[3 * Hn + u] + bhh2[3 * Hn + u]);
    }

    if (tid == 0) {
        unsigned v;
        asm volatile("ld.acquire.gpu.b32 %0, [%1];" : "=r"(v) : "l"(flg) : "memory");
        *sBase = v;
    }
    __syncthreads();
    unsigned base = *sBase;

    int kc0 = kh ? 32 : 0;
    int kc1 = kh ? KCn : 32;
    int rcg = cgf >> 1, rcell = (cgf & 1) * 2;
    unsigned long long* redDst = &sRed[(((size_t)(kh * 8 + cg) * 4) * 16 + q) * 2];
    const unsigned long long* p0 = &sRed[(((size_t)(0 * 8 + rcg) * 4 + rcell) * 16 + q) * 2];
    const unsigned long long* p1 = &sRed[(((size_t)(1 * 8 + rcg) * 4 + rcell) * 16 + q) * 2];

    const unsigned long long* row0 = &sH[(cg * 4 + 0) * KP];
    const unsigned long long* row1 = &sH[(cg * 4 + 1) * KP];
    const unsigned long long* row2 = &sH[(cg * 4 + 2) * KP];
    const unsigned long long* row3 = &sH[(cg * 4 + 3) * KP];

    float cv0 = 0.f, cv1 = 0.f;

    for (int t = 0; t < Tn; ++t) {
        // prefetch xg for this step's pointwise cells
        float4 x0 = make_float4(0.f, 0.f, 0.f, 0.f), x1 = x0;
        if (valid) {
            size_t r0i = (size_t)t * Bn + b0 + c0;
            x0 = __ldg((const float4*)(xg + r0i * Gn + u * 4));
            x1 = __ldg((const float4*)(xg + (r0i + 1) * Gn + u * 4));
        }

        // ---- stage packed h(t) tile: warp w stages rows 4w..4w+3 ----
        {
            const unsigned long long* src = g_hd + ((size_t)t * Bn + b0 + 4 * w) * HP;
            #pragma unroll
            for (int j = 0; j < 16; ++j) {
                int i = j * 32 + lane;
                if (i < 504) {
                    int row = i / 126, c2 = i - row * 126;
                    ulonglong2 v = __ldcg((const ulonglong2*)(src + (size_t)row * HP + c2 * 2));
                    *(ulonglong2*)&sH[(4 * w + row) * KP + c2 * 2] = v;
                }
            }
        }
        __syncthreads();

        // ---- recurrent gate GEMM (critical path) ----
        unsigned long long aR_if[4] = {0ull,0ull,0ull,0ull}, aR_go[4] = {0ull,0ull,0ull,0ull};
        #pragma unroll 4
        for (int kc = kc0; kc < kc1; ++kc) {
            ulonglong2 w0 = *(const ulonglong2*)&sW1[(kc * 4 + 0) * 64 + 4 * q];
            ulonglong2 w1 = *(const ulonglong2*)&sW1[(kc * 4 + 1) * 64 + 4 * q];
            ulonglong2 w2 = *(const ulonglong2*)&sW1[(kc * 4 + 2) * 64 + 4 * q];
            ulonglong2 w3 = *(const ulonglong2*)&sW1[(kc * 4 + 3) * 64 + 4 * q];
#define CELL(J, ROW)                                                                \
            {                                                                       \
                ulonglong2 lo = *(const ulonglong2*)&ROW[kc * 4];                   \
                ulonglong2 hi = *(const ulonglong2*)&ROW[kc * 4 + 2];               \
                ffma2(aR_if[J], w0.x, lo.x); ffma2(aR_go[J], w0.y, lo.x);           \
                ffma2(aR_if[J], w1.x, lo.y); ffma2(aR_go[J], w1.y, lo.y);           \
                ffma2(aR_if[J], w2.x, hi.x); ffma2(aR_go[J], w2.y, hi.x);           \
                ffma2(aR_if[J], w3.x, hi.y); ffma2(aR_go[J], w3.y, hi.y);           \
            }
            CELL(0, row0) CELL(1, row1) CELL(2, row2) CELL(3, row3)
#undef CELL
        }

        // ---- reduction: recurrent partials ----
        #pragma unroll
        for (int j = 0; j < 4; ++j) {
            redDst[(size_t)j * 32 + 0] = aR_if[j];
            redDst[(size_t)j * 32 + 1] = aR_go[j];
        }
        __syncthreads();

        unsigned long long A_if = add2(p0[0],  p1[0]);
        unsigned long long A_go = add2(p0[1],  p1[1]);
        unsigned long long B_if = add2(p0[32], p1[32]);
        unsigned long long B_go = add2(p0[33], p1[33]);

        // ---- pointwise LSTM cells + h stores ----
        {
            float gi, gf, gg, go;
            unpack2(A_if, gi, gf); unpack2(A_go, gg, go);
            float iv = sigf(gi + x0.x);
            float fv = sigf(gf + x0.y);
            float gv = tanhfast(gg + x0.z);
            float ov = sigf(go + x0.w);
            cv0 = fv * cv0 + iv * gv;
            float hv = ov * tanhfast(cv0);
            if (valid) {
                size_t wi = ((size_t)(t + 1) * Bn + b0 + c0) * HP + u;
                __stcg((unsigned long long*)(g_hd + wi), pack2(hv, hv));
            }
        }
        {
            float gi, gf, gg, go;
            unpack2(B_if, gi, gf); unpack2(B_go, gg, go);
            float iv = sigf(gi + x1.x);
            float fv = sigf(gf + x1.y);
            float gv = tanhfast(gg + x1.z);
            float ov = sigf(go + x1.w);
            cv1 = fv * cv1 + iv * gv;
            float hv = ov * tanhfast(cv1);
            if (valid) {
                size_t wi = ((size_t)(t + 1) * Bn + b0 + c0 + 1) * HP + u;
                __stcg((unsigned long long*)(g_hd + wi), pack2(hv, hv));
            }
        }

        // ---- ARRIVE: publish this CTA's h stores to the group ----
        __syncthreads();                        // all threads' h stores issued
        if (tid == 0) {
            __threadfence();                    // cumulative release
            unsigned old = atomicAdd(cnt, 1u);
            unsigned epoch = base + (unsigned)(t + 1);
            if ((old & 15u) == 15u) {
                asm volatile("st.release.gpu.b32 [%0], %1;" :: "l"(flg), "r"(epoch) : "memory");
            }
        }

        // ---- X-GEMM in the arrive->wait window (FUSED; off critical path) ----
        if (FUSED) {
            unsigned long long aX_if[4] = {0ull,0ull,0ull,0ull}, aX_go[4] = {0ull,0ull,0ull,0ull};
            #pragma unroll 4
            for (int kc = kc0; kc < kc1; ++kc) {
                ulonglong2 v0 = *(const ulonglong2*)&sW2[(kc * 4 + 0) * 64 + 4 * q];
                ulonglong2 v1 = *(const ulonglong2*)&sW2[(kc * 4 + 1) * 64 + 4 * q];
                ulonglong2 v2 = *(const ulonglong2*)&sW2[(kc * 4 + 2) * 64 + 4 * q];
                ulonglong2 v3 = *(const ulonglong2*)&sW2[(kc * 4 + 3) * 64 + 4 * q];
#define CELLX(J, ROW)                                                               \
                {                                                                   \
                    ulonglong2 lo = *(const ulonglong2*)&ROW[kc * 4];               \
                    ulonglong2 hi = *(const ulonglong2*)&ROW[kc * 4 + 2];           \
                    ffma2(aX_if[J], v0.x, lo.x); ffma2(aX_go[J], v0.y, lo.x);       \
                    ffma2(aX_if[J], v1.x, lo.y); ffma2(aX_go[J], v1.y, lo.y);       \
                    ffma2(aX_if[J], v2.x, hi.x); ffma2(aX_go[J], v2.y, hi.x);       \
                    ffma2(aX_if[J], v3.x, hi.y); ffma2(aX_go[J], v3.y, hi.y);       \
                }
                CELLX(0, row0) CELLX(1, row1) CELLX(2, row2) CELLX(3, row3)
#undef CELLX
            }
            #pragma unroll
            for (int j = 0; j < 4; ++j) {
                redDst[(size_t)j * 32 + 0] = aX_if[j];
                redDst[(size_t)j * 32 + 1] = aX_go[j];
            }
            __syncthreads();
            if (valid && t >= 1) {
                ulonglong2 o0, o1;
                o0.x = add2(add2(p0[0],  p1[0]),  b2_if);
                o0.y = add2(add2(p0[1],  p1[1]),  b2_go);
                o1.x = add2(add2(p0[32], p1[32]), b2_if);
                o1.y = add2(add2(p0[33], p1[33]), b2_go);
                size_t row = (size_t)(t - 1) * Bn + b0 + c0;
                *(ulonglong2*)(g_xg + row * Gn + u * 4) = o0;
                *(ulonglong2*)(g_xg + (row + 1) * Gn + u * 4) = o1;
            }
        }

        // ---- WAIT ----
        if (tid == 0) {
            unsigned epoch = base + (unsigned)(t + 1);
            unsigned v;
            do {
                asm volatile("ld.acquire.gpu.b32 %0, [%1];" : "=r"(v) : "l"(flg) : "memory");
            } while (v < epoch);
        }
        __syncthreads();
    }

    // ---- FUSED epilogue: xg1[Tn-1] from h0(Tn-1) = slot Tn ----
    if (FUSED) {
        {
            const unsigned long long* src = g_hd + ((size_t)Tn * Bn + b0 + 4 * w) * HP;
            #pragma unroll
            for (int j = 0; j < 16; ++j) {
                int i = j * 32 + lane;
                if (i < 504) {
                    int row = i / 126, c2 = i - row * 126;
                    ulonglong2 v = __ldcg((const ulonglong2*)(src + (size_t)row * HP + c2 * 2));
                    *(ulonglong2*)&sH[(4 * w + row) * KP + c2 * 2] = v;
                }
            }
        }
        __syncthreads();

        unsigned long long aX_if[4] = {0ull,0ull,0ull,0ull}, aX_go[4] = {0ull,0ull,0ull,0ull};
        #pragma unroll 4
        for (int kc = kc0; kc < kc1; ++kc) {
            ulonglong2 v0 = *(const ulonglong2*)&sW2[(kc * 4 + 0) * 64 + 4 * q];
            ulonglong2 v1 = *(const ulonglong2*)&sW2[(kc * 4 + 1) * 64 + 4 * q];
            ulonglong2 v2 = *(const ulonglong2*)&sW2[(kc * 4 + 2) * 64 + 4 * q];
            ulonglong2 v3 = *(const ulonglong2*)&sW2[(kc * 4 + 3) * 64 + 4 * q];
#define CELLX(J, ROW)                                                               \
            {                                                                       \
                ulonglong2 lo = *(const ulonglong2*)&ROW[kc * 4];                   \
                ulonglong2 hi = *(const ulonglong2*)&ROW[kc * 4 + 2];               \
                ffma2(aX_if[J], v0.x, lo.x); ffma2(aX_go[J], v0.y, lo.x);           \
                ffma2(aX_if[J], v1.x, lo.y); ffma2(aX_go[J], v1.y, lo.y);           \
                ffma2(aX_if[J], v2.x, hi.x); ffma2(aX_go[J], v2.y, hi.x);           \
                ffma2(aX_if[J], v3.x, hi.y); ffma2(aX_go[J], v3.y, hi.y);           \
            }
            CELLX(0, row0) CELLX(1, row1) CELLX(2, row2) CELLX(3, row3)
#undef CELLX
        }
        #pragma unroll
        for (int j = 0; j < 4; ++j) {
            redDst[(size_t)j * 32 + 0] = aX_if[j];
            redDst[(size_t)j * 32 + 1] = aX_go[j];
        }
        __syncthreads();
        if (valid) {
            ulonglong2 o0, o1;
            o0.x = add2(add2(p0[0],  p1[0]),  b2_if);
            o0.y = add2(add2(p0[1],  p1[1]),  b2_go);
            o1.x = add2(add2(p0[32], p1[32]), b2_if);
            o1.y = add2(add2(p0[33], p1[33]), b2_go);
            size_t row = (size_t)(Tn - 1) * Bn + b0 + c0;
            *(ulonglong2*)(g_xg + row * Gn + u * 4) = o0;
            *(ulonglong2*)(g_xg + (row + 1) * Gn + u * 4) = o1;
        }
    }
}

// ---------------- output head (reads packed h2) ----------------
__global__ void __launch_bounds__(256, 1)
k_head(const float* __restrict__ Wl, const float* __restrict__ bl, float* __restrict__ out) {
    __shared__ float sw[256];
    int tid = threadIdx.x;
    sw[tid] = (tid < Hn) ? Wl[tid] : 0.f;
    __syncthreads();
    int warp = tid >> 5, lane = tid & 31;
    int r = blockIdx.x * 8 + warp;          // r = b*T + t (output order)
    int t = r & (Tn - 1);
    int b = r >> 9;
    const unsigned long long* hrow = g_hd + ((size_t)(t + 1) * Bn + b) * HP;
    float p = 0.f;
    #pragma unroll
    for (int j = 0; j < 8; ++j) {
        int k = j * 32 + lane;
        float lo, hi;
        unpack2(__ldg(hrow + k), lo, hi);
        p = fmaf(sw[k], lo, p);
    }
    #pragma unroll
    for (int off = 16; off; off >>= 1) p += __shfl_xor_sync(0xffffffffu, p, off);
    if (lane == 0) out[r] = 1.f / (1.f + __expf(-(p + bl[0])));
}

// ---------------- launcher ----------------
extern "C" void kernel_launch(void* const* d_in, const int* in_sizes, int n_in,
                              void* d_out, int out_size) {
    const float* x    = (const float*)d_in[0];
    const float* Wih0 = (const float*)d_in[1];
    const float* Whh0 = (const float*)d_in[2];
    const float* bih0 = (const float*)d_in[3];
    const float* bhh0 = (const float*)d_in[4];
    const float* Wih1 = (const float*)d_in[5];
    const float* Whh1 = (const float*)d_in[6];
    const float* bih1 = (const float*)d_in[7];
    const float* bhh1 = (const float*)d_in[8];
    const float* Wlin = (const float*)d_in[9];
    const float* blin = (const float*)d_in[10];
    float* out = (float*)d_out;

    const int smem_rec1  = 145424 + KP * 64 * 4;   // 209,936 B (fused: + W_ih1 tile)
    const int smem_rec0  = 145424;                 // 145,424 B
    const int smem_gemm0 = (10 * 4 * 64 + 128 * 48 + 64) * 4;   // 35,072 B

    cudaFuncSetAttribute(k_rec<1>, cudaFuncAttributeMaxDynamicSharedMemorySize, smem_rec1);
    cudaFuncSetAttribute(k_rec<0>, cudaFuncAttributeMaxDynamicSharedMemorySize, smem_rec0);

    // layer-0 input contributions
    k_xgemm0<<<dim3(16, 1024), 256, smem_gemm0>>>(x, Wih0, bih0, bhh0);
    // layer-0 recurrence, fused with layer-1 input GEMM (X-GEMM in barrier window)
    k_rec<1><<<128, 256, smem_rec1>>>(Whh0, Wih1, bih1, bhh1, 0);
    // layer-1 recurrence
    k_rec<0><<<128, 256, smem_rec0>>>(Whh1, nullptr, nullptr, nullptr, 1);
    // head
    k_head<<<16384, 256>>>(Wlin, blin, out);
}